// round 12
// baseline (speedup 1.0000x reference)
#include <cuda_runtime.h>
#include <cuda_fp16.h>
#include <cstdint>

#define TT 512
#define BD 2
#define TOK 256
#define TPR 12
#define HID 32
#define INNER 256
#define ATT_SCALE 0.0625f
#define BN_EPS 1e-5f

// ---------------- scratch (device globals: no allocation allowed) ----------
__device__ float g_w1f[TPR * HID];
__device__ float g_c1[HID];
__device__ float g_c2[TOK];
__device__ uint32_t g_w2h[TOK * 16];     // w2^T, BN-folded, f16 pairs [n][kpair]
__device__ float g_xb[BD * TT * TOK];
__device__ float g_dots[BD * TT * TT];
// f16 hi/lo operand buffers for the HMMA attention chain (u32-aligned)
__device__ uint32_t g_qhi[BD * TT * INNER / 2], g_qlo[BD * TT * INNER / 2];
__device__ uint32_t g_khi[BD * TT * INNER / 2], g_klo[BD * TT * INNER / 2];
__device__ uint32_t g_vthi[BD * INNER * TT / 2], g_vtlo[BD * INNER * TT / 2];
__device__ uint32_t g_ahi[BD * TT * TT / 2], g_alo[BD * TT * TT / 2];

__device__ __forceinline__ uint32_t h2_bits(float a, float b) {
    __half2 h = __floats2half2_rn(a, b);
    return *reinterpret_cast<uint32_t*>(&h);
}
__device__ __forceinline__ unsigned short h_bits(float f) {
    __half h = __float2half_rn(f);
    return *reinterpret_cast<unsigned short*>(&h);
}
__device__ __forceinline__ float h_back(unsigned short b) {
    __half h = *reinterpret_cast<__half*>(&b);
    return __half2float(h);
}

// mma.sync m16n8k16 f16 (baseline PTX, works on sm_103)
__device__ __forceinline__ void mmaH(float* d, const uint32_t* a, const uint32_t* b) {
    asm volatile(
        "mma.sync.aligned.m16n8k16.row.col.f32.f16.f16.f32 "
        "{%0,%1,%2,%3}, {%4,%5,%6,%7}, {%8,%9}, {%0,%1,%2,%3};"
        : "+f"(d[0]), "+f"(d[1]), "+f"(d[2]), "+f"(d[3])
        : "r"(a[0]), "r"(a[1]), "r"(a[2]), "r"(a[3]), "r"(b[0]), "r"(b[1]));
}

// ---------------- setup: fold BN into weights, f16 B tiles ------------------
__global__ void setup_kernel(const float* __restrict__ w1, const float* __restrict__ b1,
                             const float* __restrict__ g1, const float* __restrict__ be1,
                             const float* __restrict__ m1, const float* __restrict__ v1,
                             const float* __restrict__ w2, const float* __restrict__ b2,
                             const float* __restrict__ g2, const float* __restrict__ be2,
                             const float* __restrict__ m2, const float* __restrict__ v2) {
    __shared__ float A1s[HID], A2s[TOK];
    int tid = threadIdx.x;
    if (tid < HID) {
        float a = g1[tid] * rsqrtf(v1[tid] + BN_EPS);
        A1s[tid] = a;
        g_c1[tid] = (b1[tid] - m1[tid]) * a + be1[tid];
    }
    if (tid < TOK) {
        float a = g2[tid] * rsqrtf(v2[tid] + BN_EPS);
        A2s[tid] = a;
        g_c2[tid] = (b2[tid] - m2[tid]) * a + be2[tid];
    }
    __syncthreads();
    for (int i = tid; i < TPR * HID; i += blockDim.x) g_w1f[i] = w1[i] * A1s[i % HID];
    for (int i = tid; i < TOK * 16; i += blockDim.x) {
        int n = i >> 4, p = i & 15;
        g_w2h[i] = h2_bits(w2[(2 * p) * TOK + n] * A2s[n],
                           w2[(2 * p + 1) * TOK + n] * A2s[n]);
    }
}

// ---------------- fused TPR MLP (single f16 HMMA) + max + (x+bias) ----------
#define H1_STRIDE 17
extern __shared__ uint32_t sm_u[];
__global__ __launch_bounds__(256)
void fused_tpr_kernel(const float* __restrict__ r, const float* __restrict__ x) {
    uint32_t* smH = sm_u;                       // [512][17] f16 pairs
    __shared__ float W1s[TPR * HID], C1s[HID];
    const int tid = threadIdx.x;
    const int bs = blockIdx.x;

    for (int i = tid; i < TPR * HID; i += 256) W1s[i] = g_w1f[i];
    if (tid < HID) C1s[tid] = g_c1[tid];
    __syncthreads();

    const float* rbase = r + (size_t)bs * TT * TPR;
#pragma unroll
    for (int tt = 0; tt < 2; tt++) {
        int t = tid + tt * 256;
        const float4* rp = reinterpret_cast<const float4*>(rbase + (size_t)t * TPR);
        float4 v0 = rp[0], v1 = rp[1], v2 = rp[2];
        float rv[TPR] = {v0.x, v0.y, v0.z, v0.w, v1.x, v1.y, v1.z, v1.w,
                         v2.x, v2.y, v2.z, v2.w};
        float hv[HID];
#pragma unroll
        for (int h = 0; h < HID; h++) {
            float acc = C1s[h];
#pragma unroll
            for (int d = 0; d < TPR; d++) acc = fmaf(rv[d], W1s[d * HID + h], acc);
            hv[h] = fmaxf(acc, 0.f);
        }
#pragma unroll
        for (int p = 0; p < 16; p++)
            smH[t * H1_STRIDE + p] = h2_bits(hv[2 * p], hv[2 * p + 1]);
    }

    const int wid = tid >> 5, lane = tid & 31;
    const int g = lane >> 2, tig = lane & 3;
    const int nb = wid * 32;
    uint32_t Bh[4][4];
#pragma unroll
    for (int sub = 0; sub < 4; sub++) {
        int n = nb + sub * 8 + g;
#pragma unroll
        for (int s = 0; s < 2; s++) {
            Bh[sub][s * 2 + 0] = g_w2h[n * 16 + tig + 8 * s];
            Bh[sub][s * 2 + 1] = g_w2h[n * 16 + tig + 4 + 8 * s];
        }
    }
    __syncthreads();

    float mx[4][2];
#pragma unroll
    for (int sub = 0; sub < 4; sub++) { mx[sub][0] = -3.4e38f; mx[sub][1] = -3.4e38f; }

    for (int mi = 0; mi < 32; mi++) {
        const int r0 = mi * 16 + g;
        uint32_t Ah[2][4];
#pragma unroll
        for (int s = 0; s < 2; s++) {
            int o0 = r0 * H1_STRIDE + tig + 8 * s;
            int o1 = (r0 + 8) * H1_STRIDE + tig + 8 * s;
            Ah[s][0] = smH[o0];     Ah[s][1] = smH[o1];
            Ah[s][2] = smH[o0 + 4]; Ah[s][3] = smH[o1 + 4];
        }
#pragma unroll
        for (int sub = 0; sub < 4; sub++) {
            float acc[4] = {0.f, 0.f, 0.f, 0.f};
            mmaH(acc, Ah[0], &Bh[sub][0]);
            mmaH(acc, Ah[1], &Bh[sub][2]);
            mx[sub][0] = fmaxf(mx[sub][0], fmaxf(acc[0], acc[2]));
            mx[sub][1] = fmaxf(mx[sub][1], fmaxf(acc[1], acc[3]));
        }
    }
#pragma unroll
    for (int sub = 0; sub < 4; sub++) {
#pragma unroll
        for (int j = 0; j < 2; j++) {
            float v = mx[sub][j];
            v = fmaxf(v, __shfl_xor_sync(0xffffffffu, v, 4));
            v = fmaxf(v, __shfl_xor_sync(0xffffffffu, v, 8));
            v = fmaxf(v, __shfl_xor_sync(0xffffffffu, v, 16));
            if (lane < 4) {
                int c = nb + sub * 8 + 2 * lane + j;
                g_xb[(size_t)bs * TOK + c] =
                    x[(size_t)bs * TOK + c] + fmaxf(v + g_c2[c], 0.f);
            }
        }
    }
}

// ---------------- qkv: fp32 GEMM, epilogue emits f16 hi/lo operands ---------
__global__ void qkv_kernel(const float* __restrict__ w_qkv) {
    __shared__ float As[16][65];
    __shared__ float Bs[16][64];
    const int tid = threadIdx.x;
    const int tx = tid & 15, ty = tid >> 4;
    const int m0 = blockIdx.y * 64, n0 = blockIdx.x * 64;
    float acc[4][4] = {};
    float pa[4], pb[4];
#pragma unroll
    for (int i = 0; i < 4; i++) {
        int idx = tid + i * 256;
        pa[i] = g_xb[(size_t)(m0 + (idx >> 4)) * TOK + (idx & 15)];
        pb[i] = w_qkv[(size_t)(idx >> 6) * 768 + n0 + (idx & 63)];
    }
    for (int k0 = 0; k0 < TOK; k0 += 16) {
#pragma unroll
        for (int i = 0; i < 4; i++) {
            int idx = tid + i * 256;
            As[idx & 15][idx >> 4] = pa[i];
            Bs[idx >> 6][idx & 63] = pb[i];
        }
        __syncthreads();
        if (k0 + 16 < TOK) {
#pragma unroll
            for (int i = 0; i < 4; i++) {
                int idx = tid + i * 256;
                pa[i] = g_xb[(size_t)(m0 + (idx >> 4)) * TOK + k0 + 16 + (idx & 15)];
                pb[i] = w_qkv[(size_t)(k0 + 16 + (idx >> 6)) * 768 + n0 + (idx & 63)];
            }
        }
#pragma unroll
        for (int kk = 0; kk < 16; kk++) {
            float a[4], b[4];
#pragma unroll
            for (int i = 0; i < 4; i++) { a[i] = As[kk][ty * 4 + i]; b[i] = Bs[kk][tx * 4 + i]; }
#pragma unroll
            for (int i = 0; i < 4; i++)
#pragma unroll
                for (int j = 0; j < 4; j++) acc[i][j] = fmaf(a[i], b[j], acc[i][j]);
        }
        __syncthreads();
    }
    unsigned short* qh = (unsigned short*)g_qhi;
    unsigned short* ql = (unsigned short*)g_qlo;
    unsigned short* kh = (unsigned short*)g_khi;
    unsigned short* kl = (unsigned short*)g_klo;
    unsigned short* vh = (unsigned short*)g_vthi;
    unsigned short* vl = (unsigned short*)g_vtlo;
#pragma unroll
    for (int i = 0; i < 4; i++)
#pragma unroll
        for (int j = 0; j < 4; j++) {
            int row = m0 + ty * 4 + i;       // 0..1023  (b*TT + t)
            int col = n0 + tx * 4 + j;       // 0..767
            float val = acc[i][j];
            unsigned short hb = h_bits(val);
            unsigned short lb = h_bits(val - h_back(hb));
            if (col < 256) {
                size_t o = (size_t)row * INNER + col;
                qh[o] = hb; ql[o] = lb;
            } else if (col < 512) {
                size_t o = (size_t)row * INNER + (col - 256);
                kh[o] = hb; kl[o] = lb;
            } else {
                int bb = row >> 9, t = row & 511, c = col - 512;
                size_t o = ((size_t)bb * INNER + c) * TT + t;
                vh[o] = hb; vl[o] = lb;
            }
        }
}

// ---------------- dots = q @ k^T * scale  (split-f16 HMMA, prefetched) ------
__global__ __launch_bounds__(128) void dots_kernel() {
    const int tid = threadIdx.x;
    const int wid = tid >> 5, lane = tid & 31;
    const int g = lane >> 2, tig = lane & 3;
    const int b = blockIdx.z;
    const int m0 = blockIdx.x * 32 + (wid >> 1) * 16;
    const int n0 = blockIdx.y * 64 + (wid & 1) * 32;
    const uint32_t* qh = g_qhi + (size_t)b * TT * (INNER / 2);
    const uint32_t* ql = g_qlo + (size_t)b * TT * (INNER / 2);
    const uint32_t* kh = g_khi + (size_t)b * TT * (INNER / 2);
    const uint32_t* kl = g_klo + (size_t)b * TT * (INNER / 2);
    const int r0 = m0 + g, r1 = r0 + 8;

    uint32_t Ah[2][4], Al[2][4], Bh[2][4][2], Bl[2][4][2];
    auto loadF = [&](int kp, int buf) {
        Ah[buf][0] = qh[r0 * 128 + kp + tig];     Ah[buf][1] = qh[r1 * 128 + kp + tig];
        Ah[buf][2] = qh[r0 * 128 + kp + tig + 4]; Ah[buf][3] = qh[r1 * 128 + kp + tig + 4];
        Al[buf][0] = ql[r0 * 128 + kp + tig];     Al[buf][1] = ql[r1 * 128 + kp + tig];
        Al[buf][2] = ql[r0 * 128 + kp + tig + 4]; Al[buf][3] = ql[r1 * 128 + kp + tig + 4];
#pragma unroll
        for (int sub = 0; sub < 4; sub++) {
            int n = n0 + sub * 8 + g;
            Bh[buf][sub][0] = kh[n * 128 + kp + tig];
            Bh[buf][sub][1] = kh[n * 128 + kp + tig + 4];
            Bl[buf][sub][0] = kl[n * 128 + kp + tig];
            Bl[buf][sub][1] = kl[n * 128 + kp + tig + 4];
        }
    };

    float acc[4][4] = {};
    loadF(0, 0);
#pragma unroll
    for (int it = 0; it < 16; it++) {
        int cur = it & 1;
        if (it < 15) loadF((it + 1) * 8, cur ^ 1);
#pragma unroll
        for (int sub = 0; sub < 4; sub++) {
            mmaH(acc[sub], Ah[cur], Bh[cur][sub]);
            mmaH(acc[sub], Al[cur], Bh[cur][sub]);
            mmaH(acc[sub], Ah[cur], Bl[cur][sub]);
        }
    }
    float* dst = g_dots + (size_t)b * TT * TT;
#pragma unroll
    for (int sub = 0; sub < 4; sub++) {
        int c = n0 + sub * 8 + 2 * tig;
        dst[(size_t)r0 * TT + c]     = acc[sub][0] * ATT_SCALE;
        dst[(size_t)r0 * TT + c + 1] = acc[sub][1] * ATT_SCALE;
        dst[(size_t)r1 * TT + c]     = acc[sub][2] * ATT_SCALE;
        dst[(size_t)r1 * TT + c + 1] = acc[sub][3] * ATT_SCALE;
    }
}

// ---------------- row softmax over 512, emits f16 hi/lo attn ----------------
__global__ void softmax_kernel() {
    const int row = blockIdx.x;
    const float* p = g_dots + (size_t)row * TT;
    const int tid = threadIdx.x;
    const int w = tid >> 5, l = tid & 31;
    float v[4];
#pragma unroll
    for (int i = 0; i < 4; i++) v[i] = p[tid + i * 128];
    float m = fmaxf(fmaxf(v[0], v[1]), fmaxf(v[2], v[3]));
#pragma unroll
    for (int o = 16; o; o >>= 1) m = fmaxf(m, __shfl_xor_sync(0xffffffffu, m, o));
    __shared__ float red[4], red2[4];
    if (!l) red[w] = m;
    __syncthreads();
    m = fmaxf(fmaxf(red[0], red[1]), fmaxf(red[2], red[3]));
    float s = 0.f;
#pragma unroll
    for (int i = 0; i < 4; i++) { v[i] = __expf(v[i] - m); s += v[i]; }
#pragma unroll
    for (int o = 16; o; o >>= 1) s += __shfl_xor_sync(0xffffffffu, s, o);
    if (!l) red2[w] = s;
    __syncthreads();
    s = red2[0] + red2[1] + red2[2] + red2[3];
    float inv = 1.f / s;
    unsigned short* ah = (unsigned short*)g_ahi;
    unsigned short* al = (unsigned short*)g_alo;
#pragma unroll
    for (int i = 0; i < 4; i++) {
        float a = v[i] * inv;
        unsigned short hb = h_bits(a);
        size_t o = (size_t)row * TT + tid + i * 128;
        ah[o] = hb;
        al[o] = h_bits(a - h_back(hb));
    }
}

// ---------------- out = attn @ v  (split-f16 HMMA, prefetched) --------------
__global__ __launch_bounds__(128) void out_kernel(float* __restrict__ out) {
    const int tid = threadIdx.x;
    const int wid = tid >> 5, lane = tid & 31;
    const int g = lane >> 2, tig = lane & 3;
    const int b = blockIdx.z;
    const int m0 = blockIdx.y * 32 + (wid >> 1) * 16;
    const int n0 = blockIdx.x * 64 + (wid & 1) * 32;
    const uint32_t* ah = g_ahi + (size_t)b * TT * (TT / 2);
    const uint32_t* al = g_alo + (size_t)b * TT * (TT / 2);
    const uint32_t* vh = g_vthi + (size_t)b * INNER * (TT / 2);
    const uint32_t* vl = g_vtlo + (size_t)b * INNER * (TT / 2);
    const int r0 = m0 + g, r1 = r0 + 8;

    uint32_t Ah[2][4], Al[2][4], Bh[2][4][2], Bl[2][4][2];
    auto loadF = [&](int kp, int buf) {
        Ah[buf][0] = ah[r0 * 256 + kp + tig];     Ah[buf][1] = ah[r1 * 256 + kp + tig];
        Ah[buf][2] = ah[r0 * 256 + kp + tig + 4]; Ah[buf][3] = ah[r1 * 256 + kp + tig + 4];
        Al[buf][0] = al[r0 * 256 + kp + tig];     Al[buf][1] = al[r1 * 256 + kp + tig];
        Al[buf][2] = al[r0 * 256 + kp + tig + 4]; Al[buf][3] = al[r1 * 256 + kp + tig + 4];
#pragma unroll
        for (int sub = 0; sub < 4; sub++) {
            int n = n0 + sub * 8 + g;
            Bh[buf][sub][0] = vh[n * 256 + kp + tig];
            Bh[buf][sub][1] = vh[n * 256 + kp + tig + 4];
            Bl[buf][sub][0] = vl[n * 256 + kp + tig];
            Bl[buf][sub][1] = vl[n * 256 + kp + tig + 4];
        }
    };

    float acc[4][4] = {};
    loadF(0, 0);
#pragma unroll
    for (int it = 0; it < 32; it++) {
        int cur = it & 1;
        if (it < 31) loadF((it + 1) * 8, cur ^ 1);
#pragma unroll
        for (int sub = 0; sub < 4; sub++) {
            mmaH(acc[sub], Ah[cur], Bh[cur][sub]);
            mmaH(acc[sub], Al[cur], Bh[cur][sub]);
            mmaH(acc[sub], Ah[cur], Bl[cur][sub]);
        }
    }
    float* dst = out + (size_t)b * TT * INNER;
#pragma unroll
    for (int sub = 0; sub < 4; sub++) {
        int c = n0 + sub * 8 + 2 * tig;
        dst[(size_t)r0 * INNER + c]     = acc[sub][0];
        dst[(size_t)r0 * INNER + c + 1] = acc[sub][1];
        dst[(size_t)r1 * INNER + c]     = acc[sub][2];
        dst[(size_t)r1 * INNER + c + 1] = acc[sub][3];
    }
}

// ---------------- launch ------------------------------------------------------
extern "C" void kernel_launch(void* const* d_in, const int* in_sizes, int n_in,
                              void* d_out, int out_size) {
    const float* x     = (const float*)d_in[0];
    const float* r     = (const float*)d_in[1];
    const float* w1    = (const float*)d_in[2];
    const float* b1    = (const float*)d_in[3];
    const float* g1    = (const float*)d_in[4];
    const float* be1   = (const float*)d_in[5];
    const float* m1    = (const float*)d_in[6];
    const float* v1    = (const float*)d_in[7];
    const float* w2    = (const float*)d_in[8];
    const float* b2    = (const float*)d_in[9];
    const float* g2    = (const float*)d_in[10];
    const float* be2   = (const float*)d_in[11];
    const float* m2    = (const float*)d_in[12];
    const float* v2    = (const float*)d_in[13];
    const float* w_qkv = (const float*)d_in[14];
    float* out = (float*)d_out;

    setup_kernel<<<1, 256>>>(w1, b1, g1, be1, m1, v1, w2, b2, g2, be2, m2, v2);

    int smem_bytes = (TT * H1_STRIDE) * (int)sizeof(uint32_t); // 34816
    cudaFuncSetAttribute(fused_tpr_kernel, cudaFuncAttributeMaxDynamicSharedMemorySize, smem_bytes);
    fused_tpr_kernel<<<BD * TT, 256, smem_bytes>>>(r, x);

    qkv_kernel<<<dim3(768 / 64, 1024 / 64), 256>>>(w_qkv);
    dots_kernel<<<dim3(TT / 32, TT / 64, BD), 128>>>();
    softmax_kernel<<<BD * TT, 128>>>();
    out_kernel<<<dim3(INNER / 64, TT / 32, BD), 128>>>(out);
}

// round 13
// speedup vs baseline: 1.5196x; 1.5196x over previous
#include <cuda_runtime.h>
#include <cuda_fp16.h>
#include <cstdint>

#define TT 512
#define BD 2
#define TOK 256
#define TPR 12
#define HID 32
#define INNER 256
#define ATT_SCALE 0.0625f
#define BN_EPS 1e-5f

// ---------------- scratch (device globals: no allocation allowed) ----------
__device__ float g_w1f[TPR * HID];
__device__ float g_c1[HID];
__device__ float g_c2[TOK];
__device__ uint32_t g_w2h[TOK * 16];     // w2^T, BN-folded, f16 pairs [n][kpair]
__device__ float g_xb[BD * TT * TOK];
__device__ float g_dots[BD * TT * TT];
// f16 hi/lo operand buffers for the HMMA attention chain (u32-aligned)
__device__ uint32_t g_qhi[BD * TT * INNER / 2], g_qlo[BD * TT * INNER / 2];
__device__ uint32_t g_khi[BD * TT * INNER / 2], g_klo[BD * TT * INNER / 2];
__device__ uint32_t g_vthi[BD * INNER * TT / 2], g_vtlo[BD * INNER * TT / 2];
__device__ uint32_t g_ahi[BD * TT * TT / 2], g_alo[BD * TT * TT / 2];

__device__ __forceinline__ uint32_t h2_bits(float a, float b) {
    __half2 h = __floats2half2_rn(a, b);
    return *reinterpret_cast<uint32_t*>(&h);
}
__device__ __forceinline__ unsigned short h_bits(float f) {
    __half h = __float2half_rn(f);
    return *reinterpret_cast<unsigned short*>(&h);
}
__device__ __forceinline__ float h_back(unsigned short b) {
    __half h = *reinterpret_cast<__half*>(&b);
    return __half2float(h);
}

// mma.sync m16n8k16 f16 (baseline PTX, works on sm_103)
__device__ __forceinline__ void mmaH(float* d, const uint32_t* a, const uint32_t* b) {
    asm volatile(
        "mma.sync.aligned.m16n8k16.row.col.f32.f16.f16.f32 "
        "{%0,%1,%2,%3}, {%4,%5,%6,%7}, {%8,%9}, {%0,%1,%2,%3};"
        : "+f"(d[0]), "+f"(d[1]), "+f"(d[2]), "+f"(d[3])
        : "r"(a[0]), "r"(a[1]), "r"(a[2]), "r"(a[3]), "r"(b[0]), "r"(b[1]));
}

// Fragment set for one k-step of the split-f16 GEMM (kept in registers:
// only ever instantiated as named locals, all indices compile-time).
struct FragD {
    uint32_t ah[4], al[4];
    uint32_t bh[4][2], bl[4][2];
};

template <int KSTRIDE>
__device__ __forceinline__ void load_frag(
    FragD& f,
    const uint32_t* __restrict__ ah_, const uint32_t* __restrict__ al_,
    const uint32_t* __restrict__ bh_, const uint32_t* __restrict__ bl_,
    int r0, int r1, int n0, int g, int tig, int kp)
{
    f.ah[0] = ah_[r0 * KSTRIDE + kp + tig];     f.ah[1] = ah_[r1 * KSTRIDE + kp + tig];
    f.ah[2] = ah_[r0 * KSTRIDE + kp + tig + 4]; f.ah[3] = ah_[r1 * KSTRIDE + kp + tig + 4];
    f.al[0] = al_[r0 * KSTRIDE + kp + tig];     f.al[1] = al_[r1 * KSTRIDE + kp + tig];
    f.al[2] = al_[r0 * KSTRIDE + kp + tig + 4]; f.al[3] = al_[r1 * KSTRIDE + kp + tig + 4];
#pragma unroll
    for (int sub = 0; sub < 4; sub++) {
        int n = n0 + sub * 8 + g;
        f.bh[sub][0] = bh_[n * KSTRIDE + kp + tig];
        f.bh[sub][1] = bh_[n * KSTRIDE + kp + tig + 4];
        f.bl[sub][0] = bl_[n * KSTRIDE + kp + tig];
        f.bl[sub][1] = bl_[n * KSTRIDE + kp + tig + 4];
    }
}

__device__ __forceinline__ void mma_frag(float (&acc)[4][4], const FragD& f) {
#pragma unroll
    for (int sub = 0; sub < 4; sub++) {
        mmaH(acc[sub], f.ah, f.bh[sub]);
        mmaH(acc[sub], f.al, f.bh[sub]);
        mmaH(acc[sub], f.ah, f.bl[sub]);
    }
}

// ---------------- setup: fold BN into weights, f16 B tiles ------------------
__global__ void setup_kernel(const float* __restrict__ w1, const float* __restrict__ b1,
                             const float* __restrict__ g1, const float* __restrict__ be1,
                             const float* __restrict__ m1, const float* __restrict__ v1,
                             const float* __restrict__ w2, const float* __restrict__ b2,
                             const float* __restrict__ g2, const float* __restrict__ be2,
                             const float* __restrict__ m2, const float* __restrict__ v2) {
    __shared__ float A1s[HID], A2s[TOK];
    int tid = threadIdx.x;
    if (tid < HID) {
        float a = g1[tid] * rsqrtf(v1[tid] + BN_EPS);
        A1s[tid] = a;
        g_c1[tid] = (b1[tid] - m1[tid]) * a + be1[tid];
    }
    if (tid < TOK) {
        float a = g2[tid] * rsqrtf(v2[tid] + BN_EPS);
        A2s[tid] = a;
        g_c2[tid] = (b2[tid] - m2[tid]) * a + be2[tid];
    }
    __syncthreads();
    for (int i = tid; i < TPR * HID; i += blockDim.x) g_w1f[i] = w1[i] * A1s[i % HID];
    for (int i = tid; i < TOK * 16; i += blockDim.x) {
        int n = i >> 4, p = i & 15;
        g_w2h[i] = h2_bits(w2[(2 * p) * TOK + n] * A2s[n],
                           w2[(2 * p + 1) * TOK + n] * A2s[n]);
    }
}

// ---------------- fused TPR MLP (single f16 HMMA) + max + (x+bias) ----------
#define H1_STRIDE 17
extern __shared__ uint32_t sm_u[];
__global__ __launch_bounds__(256)
void fused_tpr_kernel(const float* __restrict__ r, const float* __restrict__ x) {
    uint32_t* smH = sm_u;                       // [512][17] f16 pairs
    __shared__ float W1s[TPR * HID], C1s[HID];
    const int tid = threadIdx.x;
    const int bs = blockIdx.x;

    for (int i = tid; i < TPR * HID; i += 256) W1s[i] = g_w1f[i];
    if (tid < HID) C1s[tid] = g_c1[tid];
    __syncthreads();

    const float* rbase = r + (size_t)bs * TT * TPR;
#pragma unroll
    for (int tt = 0; tt < 2; tt++) {
        int t = tid + tt * 256;
        const float4* rp = reinterpret_cast<const float4*>(rbase + (size_t)t * TPR);
        float4 v0 = rp[0], v1 = rp[1], v2 = rp[2];
        float rv[TPR] = {v0.x, v0.y, v0.z, v0.w, v1.x, v1.y, v1.z, v1.w,
                         v2.x, v2.y, v2.z, v2.w};
        float hv[HID];
#pragma unroll
        for (int h = 0; h < HID; h++) {
            float acc = C1s[h];
#pragma unroll
            for (int d = 0; d < TPR; d++) acc = fmaf(rv[d], W1s[d * HID + h], acc);
            hv[h] = fmaxf(acc, 0.f);
        }
#pragma unroll
        for (int p = 0; p < 16; p++)
            smH[t * H1_STRIDE + p] = h2_bits(hv[2 * p], hv[2 * p + 1]);
    }

    const int wid = tid >> 5, lane = tid & 31;
    const int g = lane >> 2, tig = lane & 3;
    const int nb = wid * 32;
    uint32_t Bh[4][4];
#pragma unroll
    for (int sub = 0; sub < 4; sub++) {
        int n = nb + sub * 8 + g;
#pragma unroll
        for (int s = 0; s < 2; s++) {
            Bh[sub][s * 2 + 0] = g_w2h[n * 16 + tig + 8 * s];
            Bh[sub][s * 2 + 1] = g_w2h[n * 16 + tig + 4 + 8 * s];
        }
    }
    __syncthreads();

    float mx[4][2];
#pragma unroll
    for (int sub = 0; sub < 4; sub++) { mx[sub][0] = -3.4e38f; mx[sub][1] = -3.4e38f; }

    for (int mi = 0; mi < 32; mi++) {
        const int r0 = mi * 16 + g;
        uint32_t Ah[2][4];
#pragma unroll
        for (int s = 0; s < 2; s++) {
            int o0 = r0 * H1_STRIDE + tig + 8 * s;
            int o1 = (r0 + 8) * H1_STRIDE + tig + 8 * s;
            Ah[s][0] = smH[o0];     Ah[s][1] = smH[o1];
            Ah[s][2] = smH[o0 + 4]; Ah[s][3] = smH[o1 + 4];
        }
#pragma unroll
        for (int sub = 0; sub < 4; sub++) {
            float acc[4] = {0.f, 0.f, 0.f, 0.f};
            mmaH(acc, Ah[0], &Bh[sub][0]);
            mmaH(acc, Ah[1], &Bh[sub][2]);
            mx[sub][0] = fmaxf(mx[sub][0], fmaxf(acc[0], acc[2]));
            mx[sub][1] = fmaxf(mx[sub][1], fmaxf(acc[1], acc[3]));
        }
    }
#pragma unroll
    for (int sub = 0; sub < 4; sub++) {
#pragma unroll
        for (int j = 0; j < 2; j++) {
            float v = mx[sub][j];
            v = fmaxf(v, __shfl_xor_sync(0xffffffffu, v, 4));
            v = fmaxf(v, __shfl_xor_sync(0xffffffffu, v, 8));
            v = fmaxf(v, __shfl_xor_sync(0xffffffffu, v, 16));
            if (lane < 4) {
                int c = nb + sub * 8 + 2 * lane + j;
                g_xb[(size_t)bs * TOK + c] =
                    x[(size_t)bs * TOK + c] + fmaxf(v + g_c2[c], 0.f);
            }
        }
    }
}

// ---------------- qkv: fp32 GEMM, epilogue emits f16 hi/lo operands ---------
__global__ void qkv_kernel(const float* __restrict__ w_qkv) {
    __shared__ float As[16][65];
    __shared__ float Bs[16][64];
    const int tid = threadIdx.x;
    const int tx = tid & 15, ty = tid >> 4;
    const int m0 = blockIdx.y * 64, n0 = blockIdx.x * 64;
    float acc[4][4] = {};
    float pa[4], pb[4];
#pragma unroll
    for (int i = 0; i < 4; i++) {
        int idx = tid + i * 256;
        pa[i] = g_xb[(size_t)(m0 + (idx >> 4)) * TOK + (idx & 15)];
        pb[i] = w_qkv[(size_t)(idx >> 6) * 768 + n0 + (idx & 63)];
    }
    for (int k0 = 0; k0 < TOK; k0 += 16) {
#pragma unroll
        for (int i = 0; i < 4; i++) {
            int idx = tid + i * 256;
            As[idx & 15][idx >> 4] = pa[i];
            Bs[idx >> 6][idx & 63] = pb[i];
        }
        __syncthreads();
        if (k0 + 16 < TOK) {
#pragma unroll
            for (int i = 0; i < 4; i++) {
                int idx = tid + i * 256;
                pa[i] = g_xb[(size_t)(m0 + (idx >> 4)) * TOK + k0 + 16 + (idx & 15)];
                pb[i] = w_qkv[(size_t)(k0 + 16 + (idx >> 6)) * 768 + n0 + (idx & 63)];
            }
        }
#pragma unroll
        for (int kk = 0; kk < 16; kk++) {
            float a[4], b[4];
#pragma unroll
            for (int i = 0; i < 4; i++) { a[i] = As[kk][ty * 4 + i]; b[i] = Bs[kk][tx * 4 + i]; }
#pragma unroll
            for (int i = 0; i < 4; i++)
#pragma unroll
                for (int j = 0; j < 4; j++) acc[i][j] = fmaf(a[i], b[j], acc[i][j]);
        }
        __syncthreads();
    }
    unsigned short* qh = (unsigned short*)g_qhi;
    unsigned short* ql = (unsigned short*)g_qlo;
    unsigned short* kh = (unsigned short*)g_khi;
    unsigned short* kl = (unsigned short*)g_klo;
    unsigned short* vh = (unsigned short*)g_vthi;
    unsigned short* vl = (unsigned short*)g_vtlo;
#pragma unroll
    for (int i = 0; i < 4; i++)
#pragma unroll
        for (int j = 0; j < 4; j++) {
            int row = m0 + ty * 4 + i;       // 0..1023  (b*TT + t)
            int col = n0 + tx * 4 + j;       // 0..767
            float val = acc[i][j];
            unsigned short hb = h_bits(val);
            unsigned short lb = h_bits(val - h_back(hb));
            if (col < 256) {
                size_t o = (size_t)row * INNER + col;
                qh[o] = hb; ql[o] = lb;
            } else if (col < 512) {
                size_t o = (size_t)row * INNER + (col - 256);
                kh[o] = hb; kl[o] = lb;
            } else {
                int bb = row >> 9, t = row & 511, c = col - 512;
                size_t o = ((size_t)bb * INNER + c) * TT + t;
                vh[o] = hb; vl[o] = lb;
            }
        }
}

// ---------------- dots = q @ k^T * scale  (split-f16 HMMA, reg-pipelined) ---
__global__ __launch_bounds__(128) void dots_kernel() {
    const int tid = threadIdx.x;
    const int wid = tid >> 5, lane = tid & 31;
    const int g = lane >> 2, tig = lane & 3;
    const int b = blockIdx.z;
    const int m0 = blockIdx.x * 32 + (wid >> 1) * 16;
    const int n0 = blockIdx.y * 64 + (wid & 1) * 32;
    const uint32_t* qh = g_qhi + (size_t)b * TT * (INNER / 2);
    const uint32_t* ql = g_qlo + (size_t)b * TT * (INNER / 2);
    const uint32_t* kh = g_khi + (size_t)b * TT * (INNER / 2);
    const uint32_t* kl = g_klo + (size_t)b * TT * (INNER / 2);
    const int r0 = m0 + g, r1 = r0 + 8;

    float acc[4][4] = {};
    FragD f0, f1;   // two NAMED buffers -> stays in registers
    load_frag<128>(f0, qh, ql, kh, kl, r0, r1, n0, g, tig, 0);
#pragma unroll
    for (int it = 0; it < 16; it += 2) {
        load_frag<128>(f1, qh, ql, kh, kl, r0, r1, n0, g, tig, (it + 1) * 8);
        mma_frag(acc, f0);
        if (it + 2 < 16)
            load_frag<128>(f0, qh, ql, kh, kl, r0, r1, n0, g, tig, (it + 2) * 8);
        mma_frag(acc, f1);
    }
    float* dst = g_dots + (size_t)b * TT * TT;
#pragma unroll
    for (int sub = 0; sub < 4; sub++) {
        int c = n0 + sub * 8 + 2 * tig;
        dst[(size_t)r0 * TT + c]     = acc[sub][0] * ATT_SCALE;
        dst[(size_t)r0 * TT + c + 1] = acc[sub][1] * ATT_SCALE;
        dst[(size_t)r1 * TT + c]     = acc[sub][2] * ATT_SCALE;
        dst[(size_t)r1 * TT + c + 1] = acc[sub][3] * ATT_SCALE;
    }
}

// ---------------- row softmax over 512, emits f16 hi/lo attn ----------------
__global__ void softmax_kernel() {
    const int row = blockIdx.x;
    const float* p = g_dots + (size_t)row * TT;
    const int tid = threadIdx.x;
    const int w = tid >> 5, l = tid & 31;
    float v[4];
#pragma unroll
    for (int i = 0; i < 4; i++) v[i] = p[tid + i * 128];
    float m = fmaxf(fmaxf(v[0], v[1]), fmaxf(v[2], v[3]));
#pragma unroll
    for (int o = 16; o; o >>= 1) m = fmaxf(m, __shfl_xor_sync(0xffffffffu, m, o));
    __shared__ float red[4], red2[4];
    if (!l) red[w] = m;
    __syncthreads();
    m = fmaxf(fmaxf(red[0], red[1]), fmaxf(red[2], red[3]));
    float s = 0.f;
#pragma unroll
    for (int i = 0; i < 4; i++) { v[i] = __expf(v[i] - m); s += v[i]; }
#pragma unroll
    for (int o = 16; o; o >>= 1) s += __shfl_xor_sync(0xffffffffu, s, o);
    if (!l) red2[w] = s;
    __syncthreads();
    s = red2[0] + red2[1] + red2[2] + red2[3];
    float inv = 1.f / s;
    unsigned short* ah = (unsigned short*)g_ahi;
    unsigned short* al = (unsigned short*)g_alo;
#pragma unroll
    for (int i = 0; i < 4; i++) {
        float a = v[i] * inv;
        unsigned short hb = h_bits(a);
        size_t o = (size_t)row * TT + tid + i * 128;
        ah[o] = hb;
        al[o] = h_bits(a - h_back(hb));
    }
}

// ---------------- out = attn @ v  (split-f16 HMMA, reg-pipelined) -----------
__global__ __launch_bounds__(128) void out_kernel(float* __restrict__ out) {
    const int tid = threadIdx.x;
    const int wid = tid >> 5, lane = tid & 31;
    const int g = lane >> 2, tig = lane & 3;
    const int b = blockIdx.z;
    const int m0 = blockIdx.y * 32 + (wid >> 1) * 16;
    const int n0 = blockIdx.x * 64 + (wid & 1) * 32;
    const uint32_t* ah = g_ahi + (size_t)b * TT * (TT / 2);
    const uint32_t* al = g_alo + (size_t)b * TT * (TT / 2);
    const uint32_t* vh = g_vthi + (size_t)b * INNER * (TT / 2);
    const uint32_t* vl = g_vtlo + (size_t)b * INNER * (TT / 2);
    const int r0 = m0 + g, r1 = r0 + 8;

    float acc[4][4] = {};
    FragD f0, f1;
    load_frag<256>(f0, ah, al, vh, vl, r0, r1, n0, g, tig, 0);
#pragma unroll
    for (int it = 0; it < 32; it += 2) {
        load_frag<256>(f1, ah, al, vh, vl, r0, r1, n0, g, tig, (it + 1) * 8);
        mma_frag(acc, f0);
        if (it + 2 < 32)
            load_frag<256>(f0, ah, al, vh, vl, r0, r1, n0, g, tig, (it + 2) * 8);
        mma_frag(acc, f1);
    }
    float* dst = out + (size_t)b * TT * INNER;
#pragma unroll
    for (int sub = 0; sub < 4; sub++) {
        int c = n0 + sub * 8 + 2 * tig;
        dst[(size_t)r0 * INNER + c]     = acc[sub][0];
        dst[(size_t)r0 * INNER + c + 1] = acc[sub][1];
        dst[(size_t)r1 * INNER + c]     = acc[sub][2];
        dst[(size_t)r1 * INNER + c + 1] = acc[sub][3];
    }
}

// ---------------- launch ------------------------------------------------------
extern "C" void kernel_launch(void* const* d_in, const int* in_sizes, int n_in,
                              void* d_out, int out_size) {
    const float* x     = (const float*)d_in[0];
    const float* r     = (const float*)d_in[1];
    const float* w1    = (const float*)d_in[2];
    const float* b1    = (const float*)d_in[3];
    const float* g1    = (const float*)d_in[4];
    const float* be1   = (const float*)d_in[5];
    const float* m1    = (const float*)d_in[6];
    const float* v1    = (const float*)d_in[7];
    const float* w2    = (const float*)d_in[8];
    const float* b2    = (const float*)d_in[9];
    const float* g2    = (const float*)d_in[10];
    const float* be2   = (const float*)d_in[11];
    const float* m2    = (const float*)d_in[12];
    const float* v2    = (const float*)d_in[13];
    const float* w_qkv = (const float*)d_in[14];
    float* out = (float*)d_out;

    setup_kernel<<<1, 256>>>(w1, b1, g1, be1, m1, v1, w2, b2, g2, be2, m2, v2);

    int smem_bytes = (TT * H1_STRIDE) * (int)sizeof(uint32_t); // 34816
    cudaFuncSetAttribute(fused_tpr_kernel, cudaFuncAttributeMaxDynamicSharedMemorySize, smem_bytes);
    fused_tpr_kernel<<<BD * TT, 256, smem_bytes>>>(r, x);

    qkv_kernel<<<dim3(768 / 64, 1024 / 64), 256>>>(w_qkv);
    dots_kernel<<<dim3(TT / 32, TT / 64, BD), 128>>>();
    softmax_kernel<<<BD * TT, 128>>>();
    out_kernel<<<dim3(INNER / 64, TT / 32, BD), 128>>>(out);
}